// round 4
// baseline (speedup 1.0000x reference)
#include <cuda_runtime.h>
#include <math.h>

#define BB 256
#define TT 256
#define II 512
#define HH 512

#define TM 64      // batches per block
#define TJ 16      // h-cols per block
#define TN 64      // gate cols per block = 4 gates x TJ
#define KT 32      // k-chunk
#define NTHR 256

// persistent scratch (allocation-free rule: __device__ globals)
__device__ float g_h[2][BB * HH];
__device__ float g_c[BB * HH];
__device__ float g_bias[4 * HH];

__device__ __forceinline__ void ffma2(unsigned long long& d,
                                      unsigned long long a,
                                      unsigned long long b) {
    asm("fma.rn.f32x2 %0, %1, %2, %0;" : "+l"(d) : "l"(a), "l"(b));
}

__device__ __forceinline__ float2 ull_as_f2(unsigned long long v) {
    float2 r;
    asm("mov.b64 {%0, %1}, %2;" : "=f"(r.x), "=f"(r.y) : "l"(v));
    return r;
}

__device__ __forceinline__ float sigmoidf_(float x) {
    return 1.0f / (1.0f + expf(-x));
}

__global__ void lstm_init_kernel(const float* __restrict__ b_ih,
                                 const float* __restrict__ b_hh) {
    int i = blockIdx.x * blockDim.x + threadIdx.x;
    if (i < BB * HH) {
        g_h[0][i] = 0.0f;
        g_h[1][i] = 0.0f;
        g_c[i]    = 0.0f;
    }
    if (i < 4 * HH) g_bias[i] = b_ih[i] + b_hh[i];
}

// One timestep: g = [x_t | h] @ [W_ih | W_hh]^T + bias; gates; c,h update.
// Tile: 64 batches x 64 gate-cols (4 gates x 16 h-cols). Warps span N
// (B reads broadcast), lanes span M (A reads vectorized). Double-buffered
// smem with register prefetch hides L2 latency. FFMA2 packed fp32 math.
__global__ void __launch_bounds__(NTHR, 1) lstm_step_kernel(
    const float* __restrict__ x,     // [B,T,I]
    const float* __restrict__ W_ih,  // [4H, I]
    const float* __restrict__ W_hh,  // [4H, H]
    int t)
{
    // Aliased smem, exactly 48KB static:
    //   As : 2 x 32 x 64 floats  (k-major rows, m contiguous)      [0,16384)
    //   Bs2: 2 x 32 x 64 float2  (k-major rows, duplicated pairs)  [16384,49152)
    //   Gs : 64 x 66 floats      (gate staging; reused after loop) [0,16896)
    __shared__ __align__(16) unsigned char smem_raw[49152];
    float*  As  = (float*) smem_raw;
    float2* Bs2 = (float2*)(smem_raw + 16384);
    float*  Gs  = (float*) smem_raw;

    const float* __restrict__ h_in = g_h[t & 1];
    float* __restrict__ h_out      = g_h[(t + 1) & 1];

    const int tid = threadIdx.x;
    const int b0  = blockIdx.x * TM;   // batch base
    const int j0  = blockIdx.y * TJ;   // h-column base

    const int w    = tid >> 5;         // warp 0..7 -> n-cols 8w..8w+7
    const int lane = tid & 31;         // lane -> m-pair {2*lane, 2*lane+1}

    // loader indices: thread handles (row am, k-group akq) and (+4) twice
    const int am  = tid & 63;          // m for A, n for B
    const int akq = tid >> 6;          // 0..3

    // global row pointers
    const float* axrow = x + ((size_t)(b0 + am) * TT + t) * II;
    const float* ahrow = h_in + (size_t)(b0 + am) * HH;
    const int    grow  = ((am >> 4) << 9) + j0 + (am & 15);
    const float* bwi   = W_ih + (size_t)grow * II;
    const float* bwh   = W_hh + (size_t)grow * HH;

    unsigned long long acc[8];
#pragma unroll
    for (int i = 0; i < 8; i++) acc[i] = 0ull;

    float4 av[2], bv[2];

    // ---- prefetch chunk 0 ----
#pragma unroll
    for (int q = 0; q < 2; q++) {
        const int kq = akq + 4 * q;
        av[q] = *(const float4*)(axrow + kq * 4);
        bv[q] = *(const float4*)(bwi + kq * 4);
    }
    {   // store chunk 0 -> buf 0
#pragma unroll
        for (int q = 0; q < 2; q++) {
            const int kq = akq + 4 * q;
#pragma unroll
            for (int j = 0; j < 4; j++) {
                const float a = ((const float*)&av[q])[j];
                const float b = ((const float*)&bv[q])[j];
                As [(kq * 4 + j) * 64 + am] = a;
                Bs2[(kq * 4 + j) * 64 + am] = make_float2(b, b);
            }
        }
    }
    __syncthreads();

    for (int kc = 0; kc < 32; kc++) {
        const int cur = kc & 1;

        // ---- prefetch chunk kc+1 into registers (hidden under compute) ----
        if (kc < 31) {
            const int kn = kc + 1;
#pragma unroll
            for (int q = 0; q < 2; q++) {
                const int kq = akq + 4 * q;
                if (kn < 16) {
                    av[q] = *(const float4*)(axrow + kn * KT + kq * 4);
                    bv[q] = *(const float4*)(bwi   + kn * KT + kq * 4);
                } else {
                    av[q] = *(const float4*)(ahrow + (kn - 16) * KT + kq * 4);
                    bv[q] = *(const float4*)(bwh   + (kn - 16) * KT + kq * 4);
                }
            }
        }

        // ---- compute on buf cur ----
        {
            const float*  Ab = As  + cur * 2048 + 2 * lane;
            const float2* Bb = Bs2 + cur * 2048 + 8 * w;
#pragma unroll
            for (int kk = 0; kk < KT; kk++) {
                const unsigned long long a =
                    *(const unsigned long long*)(Ab + kk * 64);
                const ulonglong2 b01 = *(const ulonglong2*)(Bb + kk * 64 + 0);
                const ulonglong2 b23 = *(const ulonglong2*)(Bb + kk * 64 + 2);
                const ulonglong2 b45 = *(const ulonglong2*)(Bb + kk * 64 + 4);
                const ulonglong2 b67 = *(const ulonglong2*)(Bb + kk * 64 + 6);
                ffma2(acc[0], a, b01.x); ffma2(acc[1], a, b01.y);
                ffma2(acc[2], a, b23.x); ffma2(acc[3], a, b23.y);
                ffma2(acc[4], a, b45.x); ffma2(acc[5], a, b45.y);
                ffma2(acc[6], a, b67.x); ffma2(acc[7], a, b67.y);
            }
        }

        // ---- store prefetched chunk into the other buffer ----
        if (kc < 31) {
            const int nb = (kc + 1) & 1;
#pragma unroll
            for (int q = 0; q < 2; q++) {
                const int kq = akq + 4 * q;
#pragma unroll
                for (int j = 0; j < 4; j++) {
                    const float a = ((const float*)&av[q])[j];
                    const float b = ((const float*)&bv[q])[j];
                    As [nb * 2048 + (kq * 4 + j) * 64 + am] = a;
                    Bs2[nb * 2048 + (kq * 4 + j) * 64 + am] = make_float2(b, b);
                }
            }
        }
        __syncthreads();
    }

    // ---- bias + stage g into Gs[n][m] (Gs aliases As; all compute done) ----
#pragma unroll
    for (int j = 0; j < 8; j++) {
        const int n  = 8 * w + j;
        const int gr = ((n >> 4) << 9) + j0 + (n & 15);
        float2 v = ull_as_f2(acc[j]);
        const float bias = g_bias[gr];
        v.x += bias; v.y += bias;
        *(float2*)&Gs[n * 66 + 2 * lane] = v;
    }
    __syncthreads();

    // ---- elementwise LSTM update: 64 batches x 16 h-cols ----
    const int jl = tid & 15;           // h-col within tile (lanes -> coalesced gi)
    const int mb = (tid >> 4) * 4;     // batch base, 4 per thread
#pragma unroll
    for (int u = 0; u < 4; u++) {
        const int m  = mb + u;
        const float iv = sigmoidf_(Gs[( 0 + jl) * 66 + m]);
        const float fv = sigmoidf_(Gs[(16 + jl) * 66 + m]);
        const float gg = tanhf    (Gs[(32 + jl) * 66 + m]);
        const float ov = sigmoidf_(Gs[(48 + jl) * 66 + m]);
        const int gi = (b0 + m) * HH + j0 + jl;
        const float cn = fv * g_c[gi] + iv * gg;
        g_c[gi]   = cn;
        h_out[gi] = ov * tanhf(cn);
    }
}

// out[b] = dot(h_last[b,:], fc_w[0,:]) + fc_b[0]
__global__ void lstm_final_kernel(const float* __restrict__ fc_w,
                                  const float* __restrict__ fc_b,
                                  float* __restrict__ out)
{
    const int b   = blockIdx.x;
    const int tid = threadIdx.x;   // 128 threads
    const float* h_last = g_h[TT & 1];   // T even -> buffer 0

    const float4 hv = *(const float4*)&h_last[b * HH + tid * 4];
    const float4 wv = *(const float4*)&fc_w[tid * 4];
    float s = hv.x * wv.x + hv.y * wv.y + hv.z * wv.z + hv.w * wv.w;

#pragma unroll
    for (int o = 16; o > 0; o >>= 1) s += __shfl_down_sync(0xFFFFFFFFu, s, o);

    __shared__ float ws[4];
    if ((tid & 31) == 0) ws[tid >> 5] = s;
    __syncthreads();
    if (tid == 0) out[b] = ws[0] + ws[1] + ws[2] + ws[3] + fc_b[0];
}

extern "C" void kernel_launch(void* const* d_in, const int* in_sizes, int n_in,
                              void* d_out, int out_size)
{
    const float* x    = (const float*)d_in[0];
    const float* W_ih = (const float*)d_in[1];
    const float* W_hh = (const float*)d_in[2];
    const float* b_ih = (const float*)d_in[3];
    const float* b_hh = (const float*)d_in[4];
    const float* fc_w = (const float*)d_in[5];
    const float* fc_b = (const float*)d_in[6];
    float* out = (float*)d_out;

    lstm_init_kernel<<<(BB * HH + 255) / 256, 256>>>(b_ih, b_hh);

    dim3 grid(BB / TM, HH / TJ);   // 4 x 32 = 128 blocks
    for (int t = 0; t < TT; t++) {
        lstm_step_kernel<<<grid, NTHR>>>(x, W_ih, W_hh, t);
    }

    lstm_final_kernel<<<BB, 128>>>(fc_w, fc_b, out);
}

// round 5
// speedup vs baseline: 1.0841x; 1.0841x over previous
#include <cuda_runtime.h>
#include <math.h>

#define BB 256
#define TT 256
#define II 512
#define HH 512
#define NG 2048   // 4*HH

// persistent scratch (allocation-free rule: __device__ globals)
__device__ float g_h[2][BB * HH];
__device__ float g_c[BB * HH];
__device__ float g_bias[NG];
__device__ float g_xg[(size_t)TT * BB * NG];   // [t][b][n], includes bias

__device__ __forceinline__ void ffma2(unsigned long long& d,
                                      unsigned long long a,
                                      unsigned long long b) {
    asm("fma.rn.f32x2 %0, %1, %2, %0;" : "+l"(d) : "l"(a), "l"(b));
}

__device__ __forceinline__ float2 ull_as_f2(unsigned long long v) {
    float2 r;
    asm("mov.b64 {%0, %1}, %2;" : "=f"(r.x), "=f"(r.y) : "l"(v));
    return r;
}

__device__ __forceinline__ float sigmoidf_(float x) {
    return 1.0f / (1.0f + expf(-x));
}

__global__ void lstm_init_kernel(const float* __restrict__ b_ih,
                                 const float* __restrict__ b_hh) {
    int i = blockIdx.x * blockDim.x + threadIdx.x;
    if (i < BB * HH) {
        g_h[0][i] = 0.0f;
        g_h[1][i] = 0.0f;
        g_c[i]    = 0.0f;
    }
    if (i < NG) g_bias[i] = b_ih[i] + b_hh[i];
}

// ============================================================================
// xg GEMM: C[m,n] = sum_k X[m,k]*W_ih[n,k] + bias[n], m = b*TT + t (65536 rows)
// stored to g_xg[t][b][n]. Tile 128x128, k-chunk 16, 8x8 per thread, FFMA2.
// FMA-bound by design: 32 FFMA2 vs ~10 LDS wavefronts per kk per warp.
// ============================================================================
__global__ void __launch_bounds__(256) xg_gemm_kernel(
    const float* __restrict__ X,   // [65536, 512]
    const float* __restrict__ W)   // [2048, 512]
{
    __shared__ __align__(16) float  Xs [2][16][128];   // 16KB
    __shared__ __align__(16) float2 Ws2[2][16][128];   // 32KB (B duplicated pairs)

    const int tid = threadIdx.x;
    const int nt  = blockIdx.x;    // n tile 0..15
    const int mt  = blockIdx.y;    // m tile 0..511

    // loaders: row within tile + k-half
    const int lr = tid & 127;
    const int lk = (tid >> 7) * 8;     // 0 or 8
    const float* xrow = X + (size_t)(mt * 128 + lr) * II + lk;
    const float* wrow = W + (size_t)(nt * 128 + lr) * II + lk;

    // compute mapping: 16 n-threads x 16 m-threads, 8x8 outputs each
    const int ntid = tid & 15;  const int n0t = ntid * 8;
    const int mtid = tid >> 4;  const int m0t = mtid * 8;

    unsigned long long acc[4][8];   // 4 m-pairs x 8 n
#pragma unroll
    for (int i = 0; i < 4; i++)
#pragma unroll
        for (int j = 0; j < 8; j++) acc[i][j] = 0ull;

    float4 xa[2], wa[2];

    // prefetch + store chunk 0
    xa[0] = *(const float4*)(xrow);     xa[1] = *(const float4*)(xrow + 4);
    wa[0] = *(const float4*)(wrow);     wa[1] = *(const float4*)(wrow + 4);
#pragma unroll
    for (int q = 0; q < 2; q++)
#pragma unroll
        for (int j = 0; j < 4; j++) {
            const float xv = ((const float*)&xa[q])[j];
            const float wv = ((const float*)&wa[q])[j];
            Xs [0][lk + q * 4 + j][lr] = xv;
            Ws2[0][lk + q * 4 + j][lr] = make_float2(wv, wv);
        }
    __syncthreads();

    for (int kc = 0; kc < 32; kc++) {
        const int cur = kc & 1;
        if (kc < 31) {
            const float* xp = xrow + (kc + 1) * 16;
            const float* wp = wrow + (kc + 1) * 16;
            xa[0] = *(const float4*)(xp);  xa[1] = *(const float4*)(xp + 4);
            wa[0] = *(const float4*)(wp);  wa[1] = *(const float4*)(wp + 4);
        }

#pragma unroll
        for (int kk = 0; kk < 16; kk++) {
            const ulonglong2 a01 = *(const ulonglong2*)&Xs[cur][kk][m0t];
            const ulonglong2 a23 = *(const ulonglong2*)&Xs[cur][kk][m0t + 4];
            const ulonglong2* bp = (const ulonglong2*)&Ws2[cur][kk][n0t];
            const ulonglong2 b0 = bp[0], b1 = bp[1], b2 = bp[2], b3 = bp[3];
            const unsigned long long av[4] = {a01.x, a01.y, a23.x, a23.y};
            const unsigned long long bv[8] = {b0.x, b0.y, b1.x, b1.y,
                                              b2.x, b2.y, b3.x, b3.y};
#pragma unroll
            for (int mp = 0; mp < 4; mp++)
#pragma unroll
                for (int nn = 0; nn < 8; nn++)
                    ffma2(acc[mp][nn], av[mp], bv[nn]);
        }

        if (kc < 31) {
            const int nb = (kc + 1) & 1;
#pragma unroll
            for (int q = 0; q < 2; q++)
#pragma unroll
                for (int j = 0; j < 4; j++) {
                    const float xv = ((const float*)&xa[q])[j];
                    const float wv = ((const float*)&wa[q])[j];
                    Xs [nb][lk + q * 4 + j][lr] = xv;
                    Ws2[nb][lk + q * 4 + j][lr] = make_float2(wv, wv);
                }
        }
        __syncthreads();
    }

    // epilogue: + bias, store to g_xg[t][b][n]
    const float4 bias0 = *(const float4*)&g_bias[nt * 128 + n0t];
    const float4 bias1 = *(const float4*)&g_bias[nt * 128 + n0t + 4];

#pragma unroll
    for (int mp = 0; mp < 4; mp++) {
        float2 v[8];
#pragma unroll
        for (int nn = 0; nn < 8; nn++) v[nn] = ull_as_f2(acc[mp][nn]);
#pragma unroll
        for (int e = 0; e < 2; e++) {
            const int m_global = mt * 128 + m0t + 2 * mp + e;
            const int b = m_global >> 8;
            const int t = m_global & 255;
            float* dst = g_xg + ((size_t)t * BB + b) * NG + nt * 128 + n0t;
            float4 o0, o1;
            o0.x = (e ? v[0].y : v[0].x) + bias0.x;
            o0.y = (e ? v[1].y : v[1].x) + bias0.y;
            o0.z = (e ? v[2].y : v[2].x) + bias0.z;
            o0.w = (e ? v[3].y : v[3].x) + bias0.w;
            o1.x = (e ? v[4].y : v[4].x) + bias1.x;
            o1.y = (e ? v[5].y : v[5].x) + bias1.y;
            o1.z = (e ? v[6].y : v[6].x) + bias1.z;
            o1.w = (e ? v[7].y : v[7].x) + bias1.w;
            *(float4*)(dst)     = o0;
            *(float4*)(dst + 4) = o1;
        }
    }
}

// ============================================================================
// Recurrent step: g = xg[t] + h @ W_hh^T; gates; c,h update. K=512 only.
// Grid (64 n-groups, 2 m-halves) = 128 blocks. Tile 128m x 32n (4 gates x 8 h).
// Pairing along M: B read = single broadcast LDS.128 -> ~4 wf vs 8 FFMA2/kk.
// ============================================================================
__global__ void __launch_bounds__(256) lstm_step_kernel(
    const float* __restrict__ W_hh,   // [2048, 512]
    int t)
{
    __shared__ __align__(16) float  Hs [2][32][128];   // 32KB
    __shared__ __align__(16) float2 Ws2[2][32][32];    // 16KB
    float* Gs = &Hs[0][0][0];   // reuse as [128][32] gate staging after loop

    const float* __restrict__ h_in = g_h[t & 1];
    float* __restrict__ h_out      = g_h[(t + 1) & 1];

    const int tid = threadIdx.x;
    const int ng  = blockIdx.x;        // 0..63 -> h-cols j0..j0+7
    const int mh  = blockIdx.y;        // 0..1
    const int b0  = mh * 128;
    const int j0  = ng * 8;

    // Hs loader: 2 threads per row, 16 k each
    const int hm = tid >> 1;
    const int hk = (tid & 1) * 16;
    const float* hrow = h_in + (size_t)(b0 + hm) * HH + hk;

    // Ws loader: 1 thread per (n, 4k)
    const int wn = tid & 31;
    const int wk = (tid >> 5) * 4;
    const int grow = (wn >> 3) * HH + j0 + (wn & 7);   // gate*512 + hcol
    const float* wrowp = W_hh + (size_t)grow * HH + wk;

    // compute mapping: 16 n-threads (2 cols each) x 16 m-threads (8 rows each)
    const int ntid = tid & 15;  const int n0t = ntid * 2;
    const int mtid = tid >> 4;  const int m0t = mtid * 8;

    unsigned long long acc[4][2];      // 4 m-pairs x 2 n
#pragma unroll
    for (int i = 0; i < 4; i++) { acc[i][0] = 0ull; acc[i][1] = 0ull; }

    float4 ha[4], wa;

    // prefetch + store chunk 0
#pragma unroll
    for (int q = 0; q < 4; q++) ha[q] = *(const float4*)(hrow + 4 * q);
    wa = *(const float4*)(wrowp);
#pragma unroll
    for (int q = 0; q < 4; q++)
#pragma unroll
        for (int j = 0; j < 4; j++)
            Hs[0][hk + q * 4 + j][hm] = ((const float*)&ha[q])[j];
#pragma unroll
    for (int j = 0; j < 4; j++) {
        const float wv = ((const float*)&wa)[j];
        Ws2[0][wk + j][wn] = make_float2(wv, wv);
    }
    __syncthreads();

    for (int kc = 0; kc < 16; kc++) {
        const int cur = kc & 1;
        if (kc < 15) {
            const int k0 = (kc + 1) * 32;
#pragma unroll
            for (int q = 0; q < 4; q++) ha[q] = *(const float4*)(hrow + k0 + 4 * q);
            wa = *(const float4*)(wrowp + k0);
        }

#pragma unroll
        for (int kk = 0; kk < 32; kk++) {
            const ulonglong2 a01 = *(const ulonglong2*)&Hs[cur][kk][m0t];
            const ulonglong2 a23 = *(const ulonglong2*)&Hs[cur][kk][m0t + 4];
            const ulonglong2 bb  = *(const ulonglong2*)&Ws2[cur][kk][n0t];
            ffma2(acc[0][0], a01.x, bb.x); ffma2(acc[0][1], a01.x, bb.y);
            ffma2(acc[1][0], a01.y, bb.x); ffma2(acc[1][1], a01.y, bb.y);
            ffma2(acc[2][0], a23.x, bb.x); ffma2(acc[2][1], a23.x, bb.y);
            ffma2(acc[3][0], a23.y, bb.x); ffma2(acc[3][1], a23.y, bb.y);
        }

        if (kc < 15) {
            const int nb = (kc + 1) & 1;
#pragma unroll
            for (int q = 0; q < 4; q++)
#pragma unroll
                for (int j = 0; j < 4; j++)
                    Hs[nb][hk + q * 4 + j][hm] = ((const float*)&ha[q])[j];
#pragma unroll
            for (int j = 0; j < 4; j++) {
                const float wv = ((const float*)&wa)[j];
                Ws2[nb][wk + j][wn] = make_float2(wv, wv);
            }
        }
        __syncthreads();
    }

    // stage recurrent g into Gs[m][n] (aliases Hs[0]; all compute done + synced)
#pragma unroll
    for (int mp = 0; mp < 4; mp++) {
        const float2 v0 = ull_as_f2(acc[mp][0]);   // col n0t  , rows m0t+2mp, +1
        const float2 v1 = ull_as_f2(acc[mp][1]);   // col n0t+1
        *(float2*)&Gs[(m0t + 2 * mp    ) * 32 + n0t] = make_float2(v0.x, v1.x);
        *(float2*)&Gs[(m0t + 2 * mp + 1) * 32 + n0t] = make_float2(v0.y, v1.y);
    }
    __syncthreads();

    // elementwise: 128 m x 8 h-cols; add xg (has bias), gates, c/h update
    const size_t xbase = (size_t)t * BB * NG;
#pragma unroll
    for (int u = 0; u < 4; u++) {
        const int idx = tid + 256 * u;     // 0..1023
        const int m   = idx >> 3;          // 0..127
        const int jl  = idx & 7;
        const int gb  = b0 + m;
        const float* xg = g_xg + xbase + (size_t)gb * NG + j0 + jl;
        const float gi_ = Gs[m * 32 +  0 + jl] + xg[0];
        const float gf_ = Gs[m * 32 +  8 + jl] + xg[512];
        const float gg_ = Gs[m * 32 + 16 + jl] + xg[1024];
        const float go_ = Gs[m * 32 + 24 + jl] + xg[1536];
        const float iv = sigmoidf_(gi_);
        const float fv = sigmoidf_(gf_);
        const float gg = tanhf(gg_);
        const float ov = sigmoidf_(go_);
        const int gidx = gb * HH + j0 + jl;
        const float cn = fv * g_c[gidx] + iv * gg;
        g_c[gidx]   = cn;
        h_out[gidx] = ov * tanhf(cn);
    }
}

// out[b] = dot(h_last[b,:], fc_w[0,:]) + fc_b[0]
__global__ void lstm_final_kernel(const float* __restrict__ fc_w,
                                  const float* __restrict__ fc_b,
                                  float* __restrict__ out)
{
    const int b   = blockIdx.x;
    const int tid = threadIdx.x;   // 128 threads
    const float* h_last = g_h[TT & 1];   // T even -> buffer 0

    const float4 hv = *(const float4*)&h_last[b * HH + tid * 4];
    const float4 wv = *(const float4*)&fc_w[tid * 4];
    float s = hv.x * wv.x + hv.y * wv.y + hv.z * wv.z + hv.w * wv.w;

#pragma unroll
    for (int o = 16; o > 0; o >>= 1) s += __shfl_down_sync(0xFFFFFFFFu, s, o);

    __shared__ float ws[4];
    if ((tid & 31) == 0) ws[tid >> 5] = s;
    __syncthreads();
    if (tid == 0) out[b] = ws[0] + ws[1] + ws[2] + ws[3] + fc_b[0];
}

extern "C" void kernel_launch(void* const* d_in, const int* in_sizes, int n_in,
                              void* d_out, int out_size)
{
    const float* x    = (const float*)d_in[0];
    const float* W_ih = (const float*)d_in[1];
    const float* W_hh = (const float*)d_in[2];
    const float* b_ih = (const float*)d_in[3];
    const float* b_hh = (const float*)d_in[4];
    const float* fc_w = (const float*)d_in[5];
    const float* fc_b = (const float*)d_in[6];
    float* out = (float*)d_out;

    lstm_init_kernel<<<(BB * HH + 255) / 256, 256>>>(b_ih, b_hh);

    // big parallel GEMM for the x contribution (all timesteps)
    dim3 ggrid(NG / 128, (BB * TT) / 128);   // (16, 512) — x-fastest => X reuse
    xg_gemm_kernel<<<ggrid, 256>>>(x, W_ih);

    // sequential recurrent steps (K=512 each)
    dim3 sgrid(64, 2);
    for (int t = 0; t < TT; t++) {
        lstm_step_kernel<<<sgrid, 256>>>(W_hh, t);
    }

    lstm_final_kernel<<<BB, 128>>>(fc_w, fc_b, out);
}

// round 6
// speedup vs baseline: 1.0862x; 1.0020x over previous
#include <cuda_runtime.h>
#include <math.h>

#define BB 256
#define TT 256
#define II 512
#define HH 512
#define NG 2048   // 4*HH

// persistent scratch (allocation-free rule: __device__ globals)
__device__ float g_h[2][BB * HH];
__device__ float g_c[BB * HH];
__device__ float g_bias[NG];
__device__ float g_xg[(size_t)TT * BB * NG];   // [t][b][n], includes bias

__device__ __forceinline__ void ffma2(unsigned long long& d,
                                      unsigned long long a,
                                      unsigned long long b) {
    asm("fma.rn.f32x2 %0, %1, %2, %0;" : "+l"(d) : "l"(a), "l"(b));
}

__device__ __forceinline__ float2 ull_as_f2(unsigned long long v) {
    float2 r;
    asm("mov.b64 {%0, %1}, %2;" : "=f"(r.x), "=f"(r.y) : "l"(v));
    return r;
}

__device__ __forceinline__ float sigmoidf_(float x) {
    return 1.0f / (1.0f + expf(-x));
}

__global__ void lstm_init_kernel(const float* __restrict__ b_ih,
                                 const float* __restrict__ b_hh) {
    int i = blockIdx.x * blockDim.x + threadIdx.x;
    if (i < BB * HH) {
        g_h[0][i] = 0.0f;
        g_h[1][i] = 0.0f;
        g_c[i]    = 0.0f;
    }
    if (i < NG) g_bias[i] = b_ih[i] + b_hh[i];
}

// ============================================================================
// xg GEMM: C[m,n] = sum_k X[m,k]*W_ih[n,k] + bias[n], m = b*TT + t (65536 rows)
// stored to g_xg[t][b][n]. Tile 128x128, k-chunk 16, 8x8 per thread, FFMA2.
// FMA-bound by design: 32 FFMA2 vs ~10 LDS wavefronts per kk per warp.
// ============================================================================
__global__ void __launch_bounds__(256) xg_gemm_kernel(
    const float* __restrict__ X,   // [65536, 512]
    const float* __restrict__ W)   // [2048, 512]
{
    __shared__ __align__(16) float  Xs [2][16][128];   // 16KB
    __shared__ __align__(16) float2 Ws2[2][16][128];   // 32KB (B duplicated pairs)

    const int tid = threadIdx.x;
    const int nt  = blockIdx.x;    // n tile 0..15
    const int mt  = blockIdx.y;    // m tile 0..511

    // loaders: row within tile + k-half
    const int lr = tid & 127;
    const int lk = (tid >> 7) * 8;     // 0 or 8
    const float* xrow = X + (size_t)(mt * 128 + lr) * II + lk;
    const float* wrow = W + (size_t)(nt * 128 + lr) * II + lk;

    // compute mapping: 16 n-threads x 16 m-threads, 8x8 outputs each
    const int ntid = tid & 15;  const int n0t = ntid * 8;
    const int mtid = tid >> 4;  const int m0t = mtid * 8;

    unsigned long long acc[4][8];   // 4 m-pairs x 8 n
#pragma unroll
    for (int i = 0; i < 4; i++)
#pragma unroll
        for (int j = 0; j < 8; j++) acc[i][j] = 0ull;

    float4 xa[2], wa[2];

    // prefetch + store chunk 0
    xa[0] = *(const float4*)(xrow);     xa[1] = *(const float4*)(xrow + 4);
    wa[0] = *(const float4*)(wrow);     wa[1] = *(const float4*)(wrow + 4);
#pragma unroll
    for (int q = 0; q < 2; q++)
#pragma unroll
        for (int j = 0; j < 4; j++) {
            const float xv = ((const float*)&xa[q])[j];
            const float wv = ((const float*)&wa[q])[j];
            Xs [0][lk + q * 4 + j][lr] = xv;
            Ws2[0][lk + q * 4 + j][lr] = make_float2(wv, wv);
        }
    __syncthreads();

    for (int kc = 0; kc < 32; kc++) {
        const int cur = kc & 1;
        if (kc < 31) {
            const float* xp = xrow + (kc + 1) * 16;
            const float* wp = wrow + (kc + 1) * 16;
            xa[0] = *(const float4*)(xp);  xa[1] = *(const float4*)(xp + 4);
            wa[0] = *(const float4*)(wp);  wa[1] = *(const float4*)(wp + 4);
        }

#pragma unroll
        for (int kk = 0; kk < 16; kk++) {
            const ulonglong2 a01 = *(const ulonglong2*)&Xs[cur][kk][m0t];
            const ulonglong2 a23 = *(const ulonglong2*)&Xs[cur][kk][m0t + 4];
            const ulonglong2* bp = (const ulonglong2*)&Ws2[cur][kk][n0t];
            const ulonglong2 b0 = bp[0], b1 = bp[1], b2 = bp[2], b3 = bp[3];
            const unsigned long long av[4] = {a01.x, a01.y, a23.x, a23.y};
            const unsigned long long bv[8] = {b0.x, b0.y, b1.x, b1.y,
                                              b2.x, b2.y, b3.x, b3.y};
#pragma unroll
            for (int mp = 0; mp < 4; mp++)
#pragma unroll
                for (int nn = 0; nn < 8; nn++)
                    ffma2(acc[mp][nn], av[mp], bv[nn]);
        }

        if (kc < 31) {
            const int nb = (kc + 1) & 1;
#pragma unroll
            for (int q = 0; q < 2; q++)
#pragma unroll
                for (int j = 0; j < 4; j++) {
                    const float xv = ((const float*)&xa[q])[j];
                    const float wv = ((const float*)&wa[q])[j];
                    Xs [nb][lk + q * 4 + j][lr] = xv;
                    Ws2[nb][lk + q * 4 + j][lr] = make_float2(wv, wv);
                }
        }
        __syncthreads();
    }

    // epilogue: + bias, store to g_xg[t][b][n]
    const float4 bias0 = *(const float4*)&g_bias[nt * 128 + n0t];
    const float4 bias1 = *(const float4*)&g_bias[nt * 128 + n0t + 4];

#pragma unroll
    for (int mp = 0; mp < 4; mp++) {
        float2 v[8];
#pragma unroll
        for (int nn = 0; nn < 8; nn++) v[nn] = ull_as_f2(acc[mp][nn]);
#pragma unroll
        for (int e = 0; e < 2; e++) {
            const int m_global = mt * 128 + m0t + 2 * mp + e;
            const int b = m_global >> 8;
            const int t = m_global & 255;
            float* dst = g_xg + ((size_t)t * BB + b) * NG + nt * 128 + n0t;
            float4 o0, o1;
            o0.x = (e ? v[0].y : v[0].x) + bias0.x;
            o0.y = (e ? v[1].y : v[1].x) + bias0.y;
            o0.z = (e ? v[2].y : v[2].x) + bias0.z;
            o0.w = (e ? v[3].y : v[3].x) + bias0.w;
            o1.x = (e ? v[4].y : v[4].x) + bias1.x;
            o1.y = (e ? v[5].y : v[5].x) + bias1.y;
            o1.z = (e ? v[6].y : v[6].x) + bias1.z;
            o1.w = (e ? v[7].y : v[7].x) + bias1.w;
            *(float4*)(dst)     = o0;
            *(float4*)(dst + 4) = o1;
        }
    }
}

// ============================================================================
// Recurrent step: g = xg[t] + h @ W_hh^T; gates; c,h update. K=512 only.
// Grid (64 n-groups, 2 m-halves) = 128 blocks. Tile 128m x 32n (4 gates x 8 h).
// Pairing along M: B read = single broadcast LDS.128 -> ~4 wf vs 8 FFMA2/kk.
// ============================================================================
__global__ void __launch_bounds__(256) lstm_step_kernel(
    const float* __restrict__ W_hh,   // [2048, 512]
    int t)
{
    __shared__ __align__(16) float  Hs [2][32][128];   // 32KB
    __shared__ __align__(16) float2 Ws2[2][32][32];    // 16KB
    float* Gs = &Hs[0][0][0];   // reuse as [128][32] gate staging after loop

    const float* __restrict__ h_in = g_h[t & 1];
    float* __restrict__ h_out      = g_h[(t + 1) & 1];

    const int tid = threadIdx.x;
    const int ng  = blockIdx.x;        // 0..63 -> h-cols j0..j0+7
    const int mh  = blockIdx.y;        // 0..1
    const int b0  = mh * 128;
    const int j0  = ng * 8;

    // Hs loader: 2 threads per row, 16 k each
    const int hm = tid >> 1;
    const int hk = (tid & 1) * 16;
    const float* hrow = h_in + (size_t)(b0 + hm) * HH + hk;

    // Ws loader: 1 thread per (n, 4k)
    const int wn = tid & 31;
    const int wk = (tid >> 5) * 4;
    const int grow = (wn >> 3) * HH + j0 + (wn & 7);   // gate*512 + hcol
    const float* wrowp = W_hh + (size_t)grow * HH + wk;

    // compute mapping: 16 n-threads (2 cols each) x 16 m-threads (8 rows each)
    const int ntid = tid & 15;  const int n0t = ntid * 2;
    const int mtid = tid >> 4;  const int m0t = mtid * 8;

    unsigned long long acc[4][2];      // 4 m-pairs x 2 n
#pragma unroll
    for (int i = 0; i < 4; i++) { acc[i][0] = 0ull; acc[i][1] = 0ull; }

    float4 ha[4], wa;

    // prefetch + store chunk 0
#pragma unroll
    for (int q = 0; q < 4; q++) ha[q] = *(const float4*)(hrow + 4 * q);
    wa = *(const float4*)(wrowp);
#pragma unroll
    for (int q = 0; q < 4; q++)
#pragma unroll
        for (int j = 0; j < 4; j++)
            Hs[0][hk + q * 4 + j][hm] = ((const float*)&ha[q])[j];
#pragma unroll
    for (int j = 0; j < 4; j++) {
        const float wv = ((const float*)&wa)[j];
        Ws2[0][wk + j][wn] = make_float2(wv, wv);
    }
    __syncthreads();

    for (int kc = 0; kc < 16; kc++) {
        const int cur = kc & 1;
        if (kc < 15) {
            const int k0 = (kc + 1) * 32;
#pragma unroll
            for (int q = 0; q < 4; q++) ha[q] = *(const float4*)(hrow + k0 + 4 * q);
            wa = *(const float4*)(wrowp + k0);
        }

#pragma unroll
        for (int kk = 0; kk < 32; kk++) {
            const ulonglong2 a01 = *(const ulonglong2*)&Hs[cur][kk][m0t];
            const ulonglong2 a23 = *(const ulonglong2*)&Hs[cur][kk][m0t + 4];
            const ulonglong2 bb  = *(const ulonglong2*)&Ws2[cur][kk][n0t];
            ffma2(acc[0][0], a01.x, bb.x); ffma2(acc[0][1], a01.x, bb.y);
            ffma2(acc[1][0], a01.y, bb.x); ffma2(acc[1][1], a01.y, bb.y);
            ffma2(acc[2][0], a23.x, bb.x); ffma2(acc[2][1], a23.x, bb.y);
            ffma2(acc[3][0], a23.y, bb.x); ffma2(acc[3][1], a23.y, bb.y);
        }

        if (kc < 15) {
            const int nb = (kc + 1) & 1;
#pragma unroll
            for (int q = 0; q < 4; q++)
#pragma unroll
                for (int j = 0; j < 4; j++)
                    Hs[nb][hk + q * 4 + j][hm] = ((const float*)&ha[q])[j];
#pragma unroll
            for (int j = 0; j < 4; j++) {
                const float wv = ((const float*)&wa)[j];
                Ws2[nb][wk + j][wn] = make_float2(wv, wv);
            }
        }
        __syncthreads();
    }

    // stage recurrent g into Gs[m][n] (aliases Hs[0]; all compute done + synced)
#pragma unroll
    for (int mp = 0; mp < 4; mp++) {
        const float2 v0 = ull_as_f2(acc[mp][0]);   // col n0t  , rows m0t+2mp, +1
        const float2 v1 = ull_as_f2(acc[mp][1]);   // col n0t+1
        *(float2*)&Gs[(m0t + 2 * mp    ) * 32 + n0t] = make_float2(v0.x, v1.x);
        *(float2*)&Gs[(m0t + 2 * mp + 1) * 32 + n0t] = make_float2(v0.y, v1.y);
    }
    __syncthreads();

    // elementwise: 128 m x 8 h-cols; add xg (has bias), gates, c/h update
    const size_t xbase = (size_t)t * BB * NG;
#pragma unroll
    for (int u = 0; u < 4; u++) {
        const int idx = tid + 256 * u;     // 0..1023
        const int m   = idx >> 3;          // 0..127
        const int jl  = idx & 7;
        const int gb  = b0 + m;
        const float* xg = g_xg + xbase + (size_t)gb * NG + j0 + jl;
        const float gi_ = Gs[m * 32 +  0 + jl] + xg[0];
        const float gf_ = Gs[m * 32 +  8 + jl] + xg[512];
        const float gg_ = Gs[m * 32 + 16 + jl] + xg[1024];
        const float go_ = Gs[m * 32 + 24 + jl] + xg[1536];
        const float iv = sigmoidf_(gi_);
        const float fv = sigmoidf_(gf_);
        const float gg = tanhf(gg_);
        const float ov = sigmoidf_(go_);
        const int gidx = gb * HH + j0 + jl;
        const float cn = fv * g_c[gidx] + iv * gg;
        g_c[gidx]   = cn;
        h_out[gidx] = ov * tanhf(cn);
    }
}

// out[b] = dot(h_last[b,:], fc_w[0,:]) + fc_b[0]
__global__ void lstm_final_kernel(const float* __restrict__ fc_w,
                                  const float* __restrict__ fc_b,
                                  float* __restrict__ out)
{
    const int b   = blockIdx.x;
    const int tid = threadIdx.x;   // 128 threads
    const float* h_last = g_h[TT & 1];   // T even -> buffer 0

    const float4 hv = *(const float4*)&h_last[b * HH + tid * 4];
    const float4 wv = *(const float4*)&fc_w[tid * 4];
    float s = hv.x * wv.x + hv.y * wv.y + hv.z * wv.z + hv.w * wv.w;

#pragma unroll
    for (int o = 16; o > 0; o >>= 1) s += __shfl_down_sync(0xFFFFFFFFu, s, o);

    __shared__ float ws[4];
    if ((tid & 31) == 0) ws[tid >> 5] = s;
    __syncthreads();
    if (tid == 0) out[b] = ws[0] + ws[1] + ws[2] + ws[3] + fc_b[0];
}

extern "C" void kernel_launch(void* const* d_in, const int* in_sizes, int n_in,
                              void* d_out, int out_size)
{
    const float* x    = (const float*)d_in[0];
    const float* W_ih = (const float*)d_in[1];
    const float* W_hh = (const float*)d_in[2];
    const float* b_ih = (const float*)d_in[3];
    const float* b_hh = (const float*)d_in[4];
    const float* fc_w = (const float*)d_in[5];
    const float* fc_b = (const float*)d_in[6];
    float* out = (float*)d_out;

    lstm_init_kernel<<<(BB * HH + 255) / 256, 256>>>(b_ih, b_hh);

    // big parallel GEMM for the x contribution (all timesteps)
    dim3 ggrid(NG / 128, (BB * TT) / 128);   // (16, 512) — x-fastest => X reuse
    xg_gemm_kernel<<<ggrid, 256>>>(x, W_ih);

    // sequential recurrent steps (K=512 each)
    dim3 sgrid(64, 2);
    for (int t = 0; t < TT; t++) {
        lstm_step_kernel<<<sgrid, 256>>>(W_hh, t);
    }

    lstm_final_kernel<<<BB, 128>>>(fc_w, fc_b, out);
}